// round 5
// baseline (speedup 1.0000x reference)
#include <cuda_runtime.h>

// Problem constants
#define I_IN   21
#define H      50
#define G      200          // 4*H, gate order: i, f, g, o
#define BATCH  4096
#define T      336
#define OUT    24
#define VK     72           // padded length of v = [x_t(21) | h(50) | 0] -> 72 (16B aligned rows)
#define VKW    76           // weight row pad: 5*76 mod 32 = 28 -> conflict-free LDS.128
#define BT     32           // batch rows per CTA
#define NTHREADS 320        // 10 warps: 40 gate-groups x 8 batch-groups
#define NCTAS  (BATCH / BT) // 128

// shared layout (floats):
//   Wt   [G * VKW]      = 15200   combined [W_ih | W_hh | pad] row-major per gate-row
//   vs   [BT * VK]      = 2304    per-batch state vector [x_t | h | pad]
//   gates[BT * G]       = 6400
//   bias [G]            = 200     b_ih + b_hh
//   Wfc  [OUT * H]      = 1200
//   bfc  [OUT]          = 24
#define SMEM_FLOATS (G*VKW + BT*VK + BT*G + G + OUT*H + OUT)

__device__ __forceinline__ float tanh_fast(float x) {
    float y;
    asm("tanh.approx.f32 %0, %1;" : "=f"(y) : "f"(x));
    return y;
}
__device__ __forceinline__ float sig_fast(float x) {
    return fmaf(0.5f, tanh_fast(0.5f * x), 0.5f);
}

__global__ __launch_bounds__(NTHREADS, 1)
void lstm_persistent_kernel(const float* __restrict__ x,
                            const float* __restrict__ W_ih,
                            const float* __restrict__ W_hh,
                            const float* __restrict__ b_ih,
                            const float* __restrict__ b_hh,
                            const float* __restrict__ W_fc,
                            const float* __restrict__ b_fc,
                            float* __restrict__ out)
{
    extern __shared__ float smem[];
    float* Wt    = smem;                 // G*VKW
    float* vs    = Wt    + G * VKW;      // BT*VK
    float* gates = vs    + BT * VK;      // BT*G
    float* bias  = gates + BT * G;       // G
    float* Wfcs  = bias  + G;            // OUT*H
    float* bfcs  = Wfcs  + OUT * H;      // OUT

    const int tid = threadIdx.x;
    const int b0  = blockIdx.x * BT;

    // ---- one-time loads into shared ----
    for (int idx = tid; idx < G * VKW; idx += NTHREADS) {
        int g = idx / VKW, k = idx % VKW;
        float v = 0.0f;
        if (k < I_IN)            v = W_ih[g * I_IN + k];
        else if (k < I_IN + H)   v = W_hh[g * H + (k - I_IN)];
        Wt[idx] = v;
    }
    for (int idx = tid; idx < G; idx += NTHREADS)       bias[idx] = b_ih[idx] + b_hh[idx];
    for (int idx = tid; idx < OUT * H; idx += NTHREADS) Wfcs[idx] = W_fc[idx];
    if (tid < OUT) bfcs[tid] = b_fc[tid];

    // init state: h = 0, pad = 0 (x part overwritten below)
    for (int idx = tid; idx < BT * VK; idx += NTHREADS) vs[idx] = 0.0f;
    __syncthreads();
    // load x_0
    for (int idx = tid; idx < BT * I_IN; idx += NTHREADS) {
        int b = idx / I_IN, i = idx % I_IN;
        vs[b * VK + i] = x[(size_t)(b0 + b) * T * I_IN + i];
    }
    __syncthreads();

    const int g5   = tid % 40;   // gate-row group: rows [g5*5, g5*5+5)
    const int bgrp = tid / 40;   // batch group: rows  [bgrp*4, bgrp*4+4)

    float creg[5];               // cell state for phase-2 pairs (tid*5 + j)
#pragma unroll
    for (int j = 0; j < 5; j++) creg[j] = 0.0f;

    for (int t = 0; t < T; ++t) {
        // ---- prefetch x_{t+1} into registers (covered by phase-1 compute) ----
        float xr[3];
        if (t + 1 < T) {
#pragma unroll
            for (int u = 0; u < 3; u++) {
                int idx = tid + u * NTHREADS;
                if (idx < BT * I_IN) {
                    int b = idx / I_IN, i = idx % I_IN;
                    xr[u] = x[(size_t)(b0 + b) * T * I_IN + (size_t)(t + 1) * I_IN + i];
                }
            }
        }

        // ---- phase 1: gates[BT][G] = v @ Wc^T + bias ----
        float acc[5][4];
#pragma unroll
        for (int j = 0; j < 5; j++) {
            float bj = bias[g5 * 5 + j];
#pragma unroll
            for (int bb = 0; bb < 4; bb++) acc[j][bb] = bj;
        }
#pragma unroll 2
        for (int k = 0; k < VK; k += 4) {
            float4 w[5];
#pragma unroll
            for (int j = 0; j < 5; j++)
                w[j] = *(const float4*)&Wt[(g5 * 5 + j) * VKW + k];
#pragma unroll
            for (int bb = 0; bb < 4; bb++) {
                float4 v = *(const float4*)&vs[(bgrp * 4 + bb) * VK + k];
#pragma unroll
                for (int j = 0; j < 5; j++) {
                    acc[j][bb] = fmaf(w[j].x, v.x, acc[j][bb]);
                    acc[j][bb] = fmaf(w[j].y, v.y, acc[j][bb]);
                    acc[j][bb] = fmaf(w[j].z, v.z, acc[j][bb]);
                    acc[j][bb] = fmaf(w[j].w, v.w, acc[j][bb]);
                }
            }
        }
#pragma unroll
        for (int j = 0; j < 5; j++)
#pragma unroll
            for (int bb = 0; bb < 4; bb++)
                gates[(bgrp * 4 + bb) * G + g5 * 5 + j] = acc[j][bb];
        __syncthreads();

        // ---- phase 2: state update (+ commit prefetched x_{t+1}) ----
        if (t + 1 < T) {
#pragma unroll
            for (int u = 0; u < 3; u++) {
                int idx = tid + u * NTHREADS;
                if (idx < BT * I_IN)
                    vs[(idx / I_IN) * VK + (idx % I_IN)] = xr[u];
            }
        }
#pragma unroll
        for (int j = 0; j < 5; j++) {
            int p  = tid * 5 + j;          // 0..1599
            int b  = p / H;
            int hu = p % H;
            const float* gb = &gates[b * G];
            float ig = sig_fast (gb[hu]);
            float fg = sig_fast (gb[H   + hu]);
            float gg = tanh_fast(gb[2*H + hu]);
            float og = sig_fast (gb[3*H + hu]);
            float c  = fmaf(fg, creg[j], ig * gg);
            creg[j]  = c;
            vs[b * VK + I_IN + hu] = og * tanh_fast(c);
        }
        __syncthreads();
    }

    // ---- FC: out[b][o] = h_last . W_fc[o] + b_fc[o] ----
#pragma unroll
    for (int u = 0; u < 3; u++) {
        int idx = tid + u * NTHREADS;
        if (idx < BT * OUT) {
            int b = idx / OUT, o = idx % OUT;
            float a = bfcs[o];
            const float* hrow = &vs[b * VK + I_IN];
            const float* wrow = &Wfcs[o * H];
#pragma unroll
            for (int j = 0; j < H; j++) a = fmaf(hrow[j], wrow[j], a);
            out[(size_t)(b0 + b) * OUT + o] = a;
        }
    }
}

extern "C" void kernel_launch(void* const* d_in, const int* in_sizes, int n_in,
                              void* d_out, int out_size)
{
    const float* x    = (const float*)d_in[0];
    const float* W_ih = (const float*)d_in[1];
    const float* W_hh = (const float*)d_in[2];
    const float* b_ih = (const float*)d_in[3];
    const float* b_hh = (const float*)d_in[4];
    const float* W_fc = (const float*)d_in[5];
    const float* b_fc = (const float*)d_in[6];
    float* out = (float*)d_out;

    const int smem_bytes = SMEM_FLOATS * (int)sizeof(float);
    cudaFuncSetAttribute(lstm_persistent_kernel,
                         cudaFuncAttributeMaxDynamicSharedMemorySize, smem_bytes);

    lstm_persistent_kernel<<<NCTAS, NTHREADS, smem_bytes>>>(
        x, W_ih, W_hh, b_ih, b_hh, W_fc, b_fc, out);
}

// round 6
// speedup vs baseline: 1.0012x; 1.0012x over previous
#include <cuda_runtime.h>

// Problem constants
#define I_IN   21
#define H      50
#define G      200          // 4*H, gate order: i, f, g, o
#define BATCH  4096
#define T      336
#define OUT    24
#define VK     72           // padded length of v = [x_t(21) | h(50) | 0] -> 72 (16B aligned rows)
#define VKW    76           // weight row pad: 5*76 mod 32 = 28 -> conflict-free LDS.128
#define BT     32           // batch rows per CTA
#define NTHREADS 320        // 10 warps: 40 gate-groups x 8 batch-groups
#define NCTAS  (BATCH / BT) // 128

// shared layout (floats):
//   Wt   [G * VKW]      = 15200   combined [W_ih | W_hh | pad] row-major per gate-row
//   vs   [BT * VK]      = 2304    per-batch state vector [x_t | h | pad]
//   gates[BT * G]       = 6400
//   bias [G]            = 200     b_ih + b_hh
//   Wfc  [OUT * H]      = 1200
//   bfc  [OUT]          = 24
#define SMEM_FLOATS (G*VKW + BT*VK + BT*G + G + OUT*H + OUT)

__device__ __forceinline__ float tanh_fast(float x) {
    float y;
    asm("tanh.approx.f32 %0, %1;" : "=f"(y) : "f"(x));
    return y;
}
__device__ __forceinline__ float sig_fast(float x) {
    return fmaf(0.5f, tanh_fast(0.5f * x), 0.5f);
}

__global__ __launch_bounds__(NTHREADS, 1)
void lstm_persistent_kernel(const float* __restrict__ x,
                            const float* __restrict__ W_ih,
                            const float* __restrict__ W_hh,
                            const float* __restrict__ b_ih,
                            const float* __restrict__ b_hh,
                            const float* __restrict__ W_fc,
                            const float* __restrict__ b_fc,
                            float* __restrict__ out)
{
    extern __shared__ float smem[];
    float* Wt    = smem;                 // G*VKW
    float* vs    = Wt    + G * VKW;      // BT*VK
    float* gates = vs    + BT * VK;      // BT*G
    float* bias  = gates + BT * G;       // G
    float* Wfcs  = bias  + G;            // OUT*H
    float* bfcs  = Wfcs  + OUT * H;      // OUT

    const int tid = threadIdx.x;
    const int b0  = blockIdx.x * BT;

    // ---- one-time loads into shared ----
    for (int idx = tid; idx < G * VKW; idx += NTHREADS) {
        int g = idx / VKW, k = idx % VKW;
        float v = 0.0f;
        if (k < I_IN)            v = W_ih[g * I_IN + k];
        else if (k < I_IN + H)   v = W_hh[g * H + (k - I_IN)];
        Wt[idx] = v;
    }
    for (int idx = tid; idx < G; idx += NTHREADS)       bias[idx] = b_ih[idx] + b_hh[idx];
    for (int idx = tid; idx < OUT * H; idx += NTHREADS) Wfcs[idx] = W_fc[idx];
    if (tid < OUT) bfcs[tid] = b_fc[tid];

    // init state: h = 0, pad = 0 (x part overwritten below)
    for (int idx = tid; idx < BT * VK; idx += NTHREADS) vs[idx] = 0.0f;
    __syncthreads();
    // load x_0
    for (int idx = tid; idx < BT * I_IN; idx += NTHREADS) {
        int b = idx / I_IN, i = idx % I_IN;
        vs[b * VK + i] = x[(size_t)(b0 + b) * T * I_IN + i];
    }
    __syncthreads();

    const int g5   = tid % 40;   // gate-row group: rows [g5*5, g5*5+5)
    const int bgrp = tid / 40;   // batch group: rows  [bgrp*4, bgrp*4+4)

    float creg[5];               // cell state for phase-2 pairs (tid*5 + j)
#pragma unroll
    for (int j = 0; j < 5; j++) creg[j] = 0.0f;

    for (int t = 0; t < T; ++t) {
        // ---- prefetch x_{t+1} into registers (covered by phase-1 compute) ----
        float xr[3];
        if (t + 1 < T) {
#pragma unroll
            for (int u = 0; u < 3; u++) {
                int idx = tid + u * NTHREADS;
                if (idx < BT * I_IN) {
                    int b = idx / I_IN, i = idx % I_IN;
                    xr[u] = x[(size_t)(b0 + b) * T * I_IN + (size_t)(t + 1) * I_IN + i];
                }
            }
        }

        // ---- phase 1: gates[BT][G] = v @ Wc^T + bias ----
        float acc[5][4];
#pragma unroll
        for (int j = 0; j < 5; j++) {
            float bj = bias[g5 * 5 + j];
#pragma unroll
            for (int bb = 0; bb < 4; bb++) acc[j][bb] = bj;
        }
#pragma unroll 2
        for (int k = 0; k < VK; k += 4) {
            float4 w[5];
#pragma unroll
            for (int j = 0; j < 5; j++)
                w[j] = *(const float4*)&Wt[(g5 * 5 + j) * VKW + k];
#pragma unroll
            for (int bb = 0; bb < 4; bb++) {
                float4 v = *(const float4*)&vs[(bgrp * 4 + bb) * VK + k];
#pragma unroll
                for (int j = 0; j < 5; j++) {
                    acc[j][bb] = fmaf(w[j].x, v.x, acc[j][bb]);
                    acc[j][bb] = fmaf(w[j].y, v.y, acc[j][bb]);
                    acc[j][bb] = fmaf(w[j].z, v.z, acc[j][bb]);
                    acc[j][bb] = fmaf(w[j].w, v.w, acc[j][bb]);
                }
            }
        }
#pragma unroll
        for (int j = 0; j < 5; j++)
#pragma unroll
            for (int bb = 0; bb < 4; bb++)
                gates[(bgrp * 4 + bb) * G + g5 * 5 + j] = acc[j][bb];
        __syncthreads();

        // ---- phase 2: state update (+ commit prefetched x_{t+1}) ----
        if (t + 1 < T) {
#pragma unroll
            for (int u = 0; u < 3; u++) {
                int idx = tid + u * NTHREADS;
                if (idx < BT * I_IN)
                    vs[(idx / I_IN) * VK + (idx % I_IN)] = xr[u];
            }
        }
#pragma unroll
        for (int j = 0; j < 5; j++) {
            int p  = tid * 5 + j;          // 0..1599
            int b  = p / H;
            int hu = p % H;
            const float* gb = &gates[b * G];
            float ig = sig_fast (gb[hu]);
            float fg = sig_fast (gb[H   + hu]);
            float gg = tanh_fast(gb[2*H + hu]);
            float og = sig_fast (gb[3*H + hu]);
            float c  = fmaf(fg, creg[j], ig * gg);
            creg[j]  = c;
            vs[b * VK + I_IN + hu] = og * tanh_fast(c);
        }
        __syncthreads();
    }

    // ---- FC: out[b][o] = h_last . W_fc[o] + b_fc[o] ----
#pragma unroll
    for (int u = 0; u < 3; u++) {
        int idx = tid + u * NTHREADS;
        if (idx < BT * OUT) {
            int b = idx / OUT, o = idx % OUT;
            float a = bfcs[o];
            const float* hrow = &vs[b * VK + I_IN];
            const float* wrow = &Wfcs[o * H];
#pragma unroll
            for (int j = 0; j < H; j++) a = fmaf(hrow[j], wrow[j], a);
            out[(size_t)(b0 + b) * OUT + o] = a;
        }
    }
}

extern "C" void kernel_launch(void* const* d_in, const int* in_sizes, int n_in,
                              void* d_out, int out_size)
{
    const float* x    = (const float*)d_in[0];
    const float* W_ih = (const float*)d_in[1];
    const float* W_hh = (const float*)d_in[2];
    const float* b_ih = (const float*)d_in[3];
    const float* b_hh = (const float*)d_in[4];
    const float* W_fc = (const float*)d_in[5];
    const float* b_fc = (const float*)d_in[6];
    float* out = (float*)d_out;

    const int smem_bytes = SMEM_FLOATS * (int)sizeof(float);
    cudaFuncSetAttribute(lstm_persistent_kernel,
                         cudaFuncAttributeMaxDynamicSharedMemorySize, smem_bytes);

    lstm_persistent_kernel<<<NCTAS, NTHREADS, smem_bytes>>>(
        x, W_ih, W_hh, b_ih, b_hh, W_fc, b_fc, out);
}